// round 2
// baseline (speedup 1.0000x reference)
#include <cuda_runtime.h>
#include <cstdint>

// LISTA fused kernel.
//   B    = We @ x        (per pixel, K=64)
//   z    = softshrink(B, th0)
//   3x:  z = softshrink(B + S[i] @ z, th[i+1])
//
// CTA = 64 consecutive pixels (same batch image, contiguous hw), 256 threads.
// Thread tile: 16 pixels x 4 dict dims, accumulators packed f32x2 (pixel pairs).
// z tile (64px x 256) lives in shared memory across all GEMMs (rotated rows to
// kill bank conflicts on the scatter write). Weights stream through a
// double-buffered 16-wide K chunk in shared memory.

typedef unsigned long long u64;

__device__ __forceinline__ u64 pack2(float a, float b) {
    u64 r; asm("mov.b64 %0, {%1,%2};" : "=l"(r) : "f"(a), "f"(b)); return r;
}
__device__ __forceinline__ void unpack2(u64 v, float& a, float& b) {
    asm("mov.b64 {%0,%1}, %2;" : "=f"(a), "=f"(b) : "l"(v));
}
__device__ __forceinline__ u64 ffma2(u64 a, u64 b, u64 c) {
    u64 d; asm("fma.rn.f32x2 %0, %1, %2, %3;" : "=l"(d) : "l"(a), "l"(b), "l"(c));
    return d;
}
__device__ __forceinline__ float sshrink(float x, float th) {
    float t = fabsf(x) - th;
    t = t > 0.0f ? t : 0.0f;
    return copysignf(t, x);
}

#define ZS_FLOATS (256 * 128)   // 256 k-rows, 128-wide (64 px + rotation slack)
#define WS_FLOATS (16 * 256)    // one K-chunk: 16 k x 256 d

// acc[p][d] += sum_k W[d][k] * Z[k][p]
//   W: gmem row-major [256][K]
//   Z: smem rows k, row k holds px p at column ((k>>1)&62) + p
template <int K>
__device__ __forceinline__ void gemm_acc(const float* __restrict__ Wg,
                                         float* Zs, float* Ws,
                                         u64 acc[8][4],
                                         int tid, int tx, int p_base)
{
    constexpr int NCH = K / 16;
    float4 r0, r1, r2, r3;
    {   // prologue: stage chunk 0 into registers
        const float4* src = reinterpret_cast<const float4*>(Wg + tid * K);
        r0 = src[0]; r1 = src[1]; r2 = src[2]; r3 = src[3];
    }
#pragma unroll 1
    for (int ch = 0; ch < NCH; ch++) {
        float* buf = Ws + (ch & 1) * WS_FLOATS;
        __syncthreads();   // everyone done computing the chunk that used this buf
        // transpose-store: Ws[kk][d=tid] = W[tid][k0+kk]  (conflict-free)
        buf[ 0 * 256 + tid] = r0.x;  buf[ 1 * 256 + tid] = r0.y;
        buf[ 2 * 256 + tid] = r0.z;  buf[ 3 * 256 + tid] = r0.w;
        buf[ 4 * 256 + tid] = r1.x;  buf[ 5 * 256 + tid] = r1.y;
        buf[ 6 * 256 + tid] = r1.z;  buf[ 7 * 256 + tid] = r1.w;
        buf[ 8 * 256 + tid] = r2.x;  buf[ 9 * 256 + tid] = r2.y;
        buf[10 * 256 + tid] = r2.z;  buf[11 * 256 + tid] = r2.w;
        buf[12 * 256 + tid] = r3.x;  buf[13 * 256 + tid] = r3.y;
        buf[14 * 256 + tid] = r3.z;  buf[15 * 256 + tid] = r3.w;
        __syncthreads();   // chunk visible
        if (ch + 1 < NCH) {   // prefetch next chunk from gmem during compute
            const float4* src =
                reinterpret_cast<const float4*>(Wg + tid * K + (ch + 1) * 16);
            r0 = src[0]; r1 = src[1]; r2 = src[2]; r3 = src[3];
        }
        const int k0 = ch * 16;
#pragma unroll
        for (int kk = 0; kk < 16; kk++) {
            const int k = k0 + kk;
            // rotated row base: row k, columns p_base.. (warp-uniform -> broadcast)
            const float* zrow = Zs + k * 128 + ((k >> 1) & 62) + p_base;
            u64 zz[8];
#pragma unroll
            for (int i = 0; i < 8; i++)
                zz[i] = *reinterpret_cast<const u64*>(zrow + 2 * i);
            const float4 wv =
                *reinterpret_cast<const float4*>(buf + kk * 256 + 4 * tx);
            const u64 w0 = pack2(wv.x, wv.x), w1 = pack2(wv.y, wv.y);
            const u64 w2 = pack2(wv.z, wv.z), w3 = pack2(wv.w, wv.w);
#pragma unroll
            for (int i = 0; i < 8; i++) {
                acc[i][0] = ffma2(zz[i], w0, acc[i][0]);
                acc[i][1] = ffma2(zz[i], w1, acc[i][1]);
                acc[i][2] = ffma2(zz[i], w2, acc[i][2]);
                acc[i][3] = ffma2(zz[i], w3, acc[i][3]);
            }
        }
    }
    __syncthreads();   // all Zs reads done before caller overwrites z
}

__global__ void __launch_bounds__(256, 1)
lista_kernel(const float* __restrict__ x,
             const float* __restrict__ We,
             const float* __restrict__ S,
             const float* __restrict__ th,
             float* __restrict__ out)
{
    extern __shared__ float smem[];
    float* Zs = smem;
    float* Ws = smem + ZS_FLOATS;

    const int tid    = threadIdx.x;
    const int tx     = tid & 63;          // dict group: d = 4*tx + 0..3
    const int ty     = tid >> 6;          // pixel group: p = 16*ty + 0..15
    const int p_base = ty * 16;

    const int pix0 = blockIdx.x * 64;
    const int b    = pix0 >> 16;          // 65536 px per image, 64 | 65536
    const int hw0  = pix0 & 65535;

    // ---- load X tile: Zs rows 0..63 hold channel c (rotated layout) ----
    {
        const int c  = tid >> 2;
        const int ps = (tid & 3) * 16;
        const float4* src = reinterpret_cast<const float4*>(
            x + b * (64 * 65536) + c * 65536 + hw0 + ps);
        const float4 v0 = src[0], v1 = src[1], v2 = src[2], v3 = src[3];
        float* dst = Zs + c * 128 + ((c >> 1) & 62) + ps;
        dst[ 0] = v0.x; dst[ 1] = v0.y; dst[ 2] = v0.z; dst[ 3] = v0.w;
        dst[ 4] = v1.x; dst[ 5] = v1.y; dst[ 6] = v1.z; dst[ 7] = v1.w;
        dst[ 8] = v2.x; dst[ 9] = v2.y; dst[10] = v2.z; dst[11] = v2.w;
        dst[12] = v3.x; dst[13] = v3.y; dst[14] = v3.z; dst[15] = v3.w;
    }
    // visibility guaranteed by the __syncthreads inside gemm_acc before compute

    u64 acc[8][4];
#pragma unroll
    for (int i = 0; i < 8; i++)
#pragma unroll
        for (int j = 0; j < 4; j++) acc[i][j] = 0ull;

    // ---- B = We @ x ----
    gemm_acc<64>(We, Zs, Ws, acc, tid, tx, p_base);

    u64 bacc[8][4];
#pragma unroll
    for (int i = 0; i < 8; i++)
#pragma unroll
        for (int j = 0; j < 4; j++) bacc[i][j] = acc[i][j];

    // ---- z0 = softshrink(B, th0) -> Zs ----
    {
        const float theta = th[0];
#pragma unroll
        for (int j = 0; j < 4; j++) {
            const int d = 4 * tx + j;
            float* row = Zs + d * 128 + ((d >> 1) & 62) + p_base;
#pragma unroll
            for (int i = 0; i < 8; i++) {
                float a, c2; unpack2(acc[i][j], a, c2);
                *reinterpret_cast<u64*>(row + 2 * i) =
                    pack2(sshrink(a, theta), sshrink(c2, theta));
            }
        }
    }

    // ---- 3 LISTA iterations ----
#pragma unroll 1
    for (int it = 0; it < 3; it++) {
#pragma unroll
        for (int i = 0; i < 8; i++)
#pragma unroll
            for (int j = 0; j < 4; j++) acc[i][j] = bacc[i][j];  // acc = B

        gemm_acc<256>(S + it * 65536, Zs, Ws, acc, tid, tx, p_base);

        const float theta = th[it + 1];
        if (it < 2) {
#pragma unroll
            for (int j = 0; j < 4; j++) {
                const int d = 4 * tx + j;
                float* row = Zs + d * 128 + ((d >> 1) & 62) + p_base;
#pragma unroll
                for (int i = 0; i < 8; i++) {
                    float a, c2; unpack2(acc[i][j], a, c2);
                    *reinterpret_cast<u64*>(row + 2 * i) =
                        pack2(sshrink(a, theta), sshrink(c2, theta));
                }
            }
        } else {
            // final iteration: write softshrink(acc) straight to gmem
            float* outb = out + b * (256 * 65536) + hw0;
#pragma unroll
            for (int j = 0; j < 4; j++) {
                const int d = 4 * tx + j;
                float4* orow =
                    reinterpret_cast<float4*>(outb + d * 65536 + p_base);
#pragma unroll
                for (int u = 0; u < 4; u++) {
                    float a0, a1, a2, a3;
                    unpack2(acc[2 * u][j],     a0, a1);
                    unpack2(acc[2 * u + 1][j], a2, a3);
                    orow[u] = make_float4(sshrink(a0, theta), sshrink(a1, theta),
                                          sshrink(a2, theta), sshrink(a3, theta));
                }
            }
        }
    }
}

extern "C" void kernel_launch(void* const* d_in, const int* in_sizes, int n_in,
                              void* d_out, int out_size)
{
    (void)in_sizes; (void)n_in; (void)out_size;
    const float* x  = (const float*)d_in[0];
    const float* We = (const float*)d_in[1];
    const float* S  = (const float*)d_in[2];
    const float* th = (const float*)d_in[3];
    float* out      = (float*)d_out;

    const size_t smem_bytes = (ZS_FLOATS + 2 * WS_FLOATS) * sizeof(float); // 160 KB
    cudaFuncSetAttribute(lista_kernel,
                         cudaFuncAttributeMaxDynamicSharedMemorySize,
                         (int)smem_bytes);
    lista_kernel<<<4096, 256, smem_bytes>>>(x, We, S, th, out);
}

// round 4
// speedup vs baseline: 2.6650x; 2.6650x over previous
#include <cuda_runtime.h>
#include <cstdint>

typedef uint32_t u32;

// ------------------------------------------------------------------
// LISTA fused, tensor-core (legacy mma.sync tf32) version.
//   B    = We @ x            (K=64)
//   z    = softshrink(B, th0)
//   3x:  z = softshrink(B + S[i] @ z, th[i+1])
//
// CTA = 128 pixels x 256 dict, 512 threads = 16 warps (4 dict-groups x
// 4 px-groups), warp tile 64d x 32px via m16n8k8 tf32 mma.sync.
// z tile (256 x 128, tf32) persistent in smem; B held in registers;
// weight K-chunks (256 x 32) staged through smem with gmem prefetch.
// ------------------------------------------------------------------

#define ZSTRIDE 136                    // floats; conflict-free B-frag loads
#define WSTRIDE 36                     // floats; conflict-free A-frag loads
#define Z_FLOATS (256 * ZSTRIDE)       // 34816
#define W_FLOATS (256 * WSTRIDE)       // 9216
#define SMEM_BYTES ((Z_FLOATS + W_FLOATS) * 4)   // 176128

__device__ __forceinline__ u32 f2tf32(float f) {
    u32 r;
    asm("cvt.rna.tf32.f32 %0, %1;" : "=r"(r) : "f"(f));
    return r;
}
__device__ __forceinline__ float tf(float f) {          // round fp32 -> tf32 value
    return __uint_as_float(f2tf32(f));
}
__device__ __forceinline__ float sshrink(float f, float th) {
    return f - fminf(fmaxf(f, -th), th);
}

__device__ __forceinline__ void mma8(float* c, const u32* a, const u32* b) {
    asm volatile(
        "mma.sync.aligned.m16n8k8.row.col.f32.tf32.tf32.f32 "
        "{%0,%1,%2,%3}, {%4,%5,%6,%7}, {%8,%9}, {%0,%1,%2,%3};"
        : "+f"(c[0]), "+f"(c[1]), "+f"(c[2]), "+f"(c[3])
        : "r"(a[0]), "r"(a[1]), "r"(a[2]), "r"(a[3]), "r"(b[0]), "r"(b[1]));
}

// D[256d x 128px] (+)= W[256d x K]^T-free: D = W @ z, z in smem [k][px].
// W gmem row-major [256][rs], streamed in NCH chunks of 32 k.
template <int NCH>
__device__ __forceinline__ void run_gemm(const float* __restrict__ Wg, int rs,
                                         float* Zs, float* Ws,
                                         float acc[4][4][4],
                                         int tid, int lane, int wd, int wp)
{
    const int d    = tid >> 1;         // weight row this thread stages
    const int half = tid & 1;          // 16-float half of the 32-k chunk
    const float* wrow = Wg + (size_t)d * rs + half * 16;
    float* wdst = Ws + d * WSTRIDE + half * 16;

    float4 p[4];
#pragma unroll
    for (int j = 0; j < 4; j++)
        p[j] = *reinterpret_cast<const float4*>(wrow + j * 4);

    const int aoff0 = (wd * 64 + (lane >> 2)) * WSTRIDE + (lane & 3);
    const int zoff0 = (lane & 3) * ZSTRIDE + wp * 32 + (lane >> 2);
    const u32* Wu = reinterpret_cast<const u32*>(Ws);
    const u32* Zu = reinterpret_cast<const u32*>(Zs);

#pragma unroll 1
    for (int ch = 0; ch < NCH; ch++) {
        __syncthreads();               // chunk buffer free, z writes visible
#pragma unroll
        for (int j = 0; j < 4; j++) {
            float4 v = make_float4(tf(p[j].x), tf(p[j].y), tf(p[j].z), tf(p[j].w));
            *reinterpret_cast<float4*>(wdst + j * 4) = v;
        }
        if (ch + 1 < NCH) {            // prefetch next chunk (hidden under MMAs)
#pragma unroll
            for (int j = 0; j < 4; j++)
                p[j] = *reinterpret_cast<const float4*>(wrow + (ch + 1) * 32 + j * 4);
        }
        __syncthreads();               // chunk visible

#pragma unroll
        for (int ks = 0; ks < 4; ks++) {
            u32 a[4][4], b[4][2];
            const int ab = aoff0 + ks * 8;
#pragma unroll
            for (int mt = 0; mt < 4; mt++) {
                const int base = ab + mt * 16 * WSTRIDE;
                a[mt][0] = Wu[base];
                a[mt][1] = Wu[base + 8 * WSTRIDE];
                a[mt][2] = Wu[base + 4];
                a[mt][3] = Wu[base + 8 * WSTRIDE + 4];
            }
            const int zb = zoff0 + (ch * 32 + ks * 8) * ZSTRIDE;
#pragma unroll
            for (int nt = 0; nt < 4; nt++) {
                b[nt][0] = Zu[zb + nt * 8];
                b[nt][1] = Zu[zb + 4 * ZSTRIDE + nt * 8];
            }
#pragma unroll
            for (int mt = 0; mt < 4; mt++)
#pragma unroll
                for (int nt = 0; nt < 4; nt++)
                    mma8(acc[mt][nt], a[mt], b[nt]);
        }
    }
}

__global__ void __launch_bounds__(512, 1)
lista_mma(const float* __restrict__ x,
          const float* __restrict__ We,
          const float* __restrict__ S,
          const float* __restrict__ th,
          float* __restrict__ out)
{
    extern __shared__ float smem[];
    float* Zs = smem;
    float* Ws = smem + Z_FLOATS;

    const int tid  = threadIdx.x;
    const int lane = tid & 31;
    const int wid  = tid >> 5;
    const int wd   = wid & 3;          // dict group (64 d each)
    const int wp   = wid >> 2;         // pixel group (32 px each)

    const int pix0 = blockIdx.x * 128;
    const int b    = pix0 >> 16;       // 65536 px per image
    const int hw0  = pix0 & 65535;

    const float th0 = __ldg(th + 0), th1 = __ldg(th + 1);
    const float th2 = __ldg(th + 2), th3 = __ldg(th + 3);

    // ---- stage x (tf32) into z rows 0..63: Zs[c][px] ----
    {
        const int c   = tid >> 3;      // 0..63
        const int seg = tid & 7;       // 16 px each
        const float* xs = x + (size_t)b * 64 * 65536 + (size_t)c * 65536
                            + hw0 + seg * 16;
        float* zd = Zs + c * ZSTRIDE + seg * 16;
#pragma unroll
        for (int j = 0; j < 4; j++) {
            float4 v = *reinterpret_cast<const float4*>(xs + j * 4);
            *reinterpret_cast<float4*>(zd + j * 4) =
                make_float4(tf(v.x), tf(v.y), tf(v.z), tf(v.w));
        }
    }
    // visibility handled by run_gemm's first __syncthreads

    float acc[4][4][4];
#pragma unroll
    for (int mt = 0; mt < 4; mt++)
#pragma unroll
        for (int nt = 0; nt < 4; nt++)
#pragma unroll
            for (int r = 0; r < 4; r++) acc[mt][nt][r] = 0.0f;

    // ---- GEMM0: B = We @ x  (K = 64) ----
    run_gemm<2>(We, 64, Zs, Ws, acc, tid, lane, wd, wp);

    float bacc[4][4][4];
#pragma unroll
    for (int mt = 0; mt < 4; mt++)
#pragma unroll
        for (int nt = 0; nt < 4; nt++)
#pragma unroll
            for (int r = 0; r < 4; r++) bacc[mt][nt][r] = acc[mt][nt][r];

    // ---- z0 = softshrink(B, th0) -> z smem ----
    __syncthreads();                   // all GEMM0 z reads done
#pragma unroll
    for (int mt = 0; mt < 4; mt++) {
        const int d0 = wd * 64 + mt * 16 + (lane >> 2);
#pragma unroll
        for (int nt = 0; nt < 4; nt++) {
            const int px = wp * 32 + nt * 8 + 2 * (lane & 3);
            float* z0 = Zs + d0 * ZSTRIDE + px;
            float* z1 = z0 + 8 * ZSTRIDE;
            *reinterpret_cast<float2*>(z0) = make_float2(
                tf(sshrink(acc[mt][nt][0], th0)), tf(sshrink(acc[mt][nt][1], th0)));
            *reinterpret_cast<float2*>(z1) = make_float2(
                tf(sshrink(acc[mt][nt][2], th0)), tf(sshrink(acc[mt][nt][3], th0)));
        }
    }

    // ---- 3 LISTA iterations ----
#pragma unroll 1
    for (int it = 0; it < 3; it++) {
#pragma unroll
        for (int mt = 0; mt < 4; mt++)
#pragma unroll
            for (int nt = 0; nt < 4; nt++)
#pragma unroll
                for (int r = 0; r < 4; r++) acc[mt][nt][r] = bacc[mt][nt][r];

        run_gemm<8>(S + (size_t)it * 65536, 256, Zs, Ws, acc, tid, lane, wd, wp);

        const float theta = (it == 0) ? th1 : (it == 1) ? th2 : th3;

        if (it < 2) {
            __syncthreads();           // all z reads of this GEMM done
#pragma unroll
            for (int mt = 0; mt < 4; mt++) {
                const int d0 = wd * 64 + mt * 16 + (lane >> 2);
#pragma unroll
                for (int nt = 0; nt < 4; nt++) {
                    const int px = wp * 32 + nt * 8 + 2 * (lane & 3);
                    float* z0 = Zs + d0 * ZSTRIDE + px;
                    float* z1 = z0 + 8 * ZSTRIDE;
                    *reinterpret_cast<float2*>(z0) = make_float2(
                        tf(sshrink(acc[mt][nt][0], theta)),
                        tf(sshrink(acc[mt][nt][1], theta)));
                    *reinterpret_cast<float2*>(z1) = make_float2(
                        tf(sshrink(acc[mt][nt][2], theta)),
                        tf(sshrink(acc[mt][nt][3], theta)));
                }
            }
        } else {
            // final: out = softshrink(B + feat), straight to gmem
            float* ob = out + (size_t)b * 256 * 65536 + hw0;
#pragma unroll
            for (int mt = 0; mt < 4; mt++) {
                const int d0 = wd * 64 + mt * 16 + (lane >> 2);
#pragma unroll
                for (int nt = 0; nt < 4; nt++) {
                    const int px = wp * 32 + nt * 8 + 2 * (lane & 3);
                    *reinterpret_cast<float2*>(ob + (size_t)d0 * 65536 + px) =
                        make_float2(sshrink(acc[mt][nt][0], theta),
                                    sshrink(acc[mt][nt][1], theta));
                    *reinterpret_cast<float2*>(ob + (size_t)(d0 + 8) * 65536 + px) =
                        make_float2(sshrink(acc[mt][nt][2], theta),
                                    sshrink(acc[mt][nt][3], theta));
                }
            }
        }
    }
}

extern "C" void kernel_launch(void* const* d_in, const int* in_sizes, int n_in,
                              void* d_out, int out_size)
{
    (void)in_sizes; (void)n_in; (void)out_size;
    const float* x  = (const float*)d_in[0];
    const float* We = (const float*)d_in[1];
    const float* S  = (const float*)d_in[2];
    const float* th = (const float*)d_in[3];
    float* out      = (float*)d_out;

    cudaFuncSetAttribute(lista_mma, cudaFuncAttributeMaxDynamicSharedMemorySize,
                         SMEM_BYTES);
    lista_mma<<<2048, 512, SMEM_BYTES>>>(x, We, S, th, out);
}